// round 1
// baseline (speedup 1.0000x reference)
#include <cuda_runtime.h>
#include <math.h>

// ---------------- problem constants ----------------
#define NB     2
#define NSEQ   2048
#define DMODEL 768
#define NH     12
#define DHEAD  64
#define MF     266        // random features
#define MP     268        // padded (multiple of 4)
#define NFF    3072
#define NCH    32         // chunks
#define CHK    64         // chunk length
#define ROWS   (NB*NSEQ)  // 4096

#define DN_SCALE   0.3535533905932738f      // 64^-0.25
#define RATIO      0.06131393394849658f     // 266^-0.5
#define EPS_KER    1e-4f
#define EPS_DEN    1e-6f

// ---------------- scratch (device globals; allocation-free) ----------------
__device__ float g_h [ROWS*DMODEL];
__device__ float g_q [ROWS*DMODEL];
__device__ float g_k [ROWS*DMODEL];
__device__ float g_v [ROWS*DMODEL];
__device__ float g_qp[NB*NH*NSEQ*MP];
__device__ float g_kp[NB*NH*NSEQ*MP];
__device__ float g_S [NB*NH*NCH*MF*DHEAD];
__device__ float g_z [NB*NH*NCH*MF];
__device__ float g_o [ROWS*DMODEL];
__device__ float g_x2[ROWS*DMODEL];
__device__ float g_h2[ROWS*DMODEL];
__device__ float g_ff[ROWS*NFF];
__device__ unsigned g_gmax;

// ---------------- helpers ----------------
__device__ __forceinline__ unsigned ford(float f){
    unsigned u = __float_as_uint(f);
    return (u & 0x80000000u) ? ~u : (u | 0x80000000u);
}
__device__ __forceinline__ float forddec(unsigned u){
    return (u & 0x80000000u) ? __uint_as_float(u & 0x7fffffffu) : __uint_as_float(~u);
}

__global__ void init_kernel(){ g_gmax = 0u; }

// ---------------- LayerNorm: one block per row (768 = 3*256) ----------------
__global__ void __launch_bounds__(256) ln_kernel(const float* __restrict__ x,
                                                 const float* __restrict__ gam,
                                                 const float* __restrict__ bet,
                                                 float* __restrict__ out){
    int row = blockIdx.x, tid = threadIdx.x;
    const float* xr = x + (size_t)row*DMODEL;
    float v0 = xr[tid], v1 = xr[tid+256], v2 = xr[tid+512];
    __shared__ float red[256];
    red[tid] = v0+v1+v2; __syncthreads();
    for(int o=128;o>0;o>>=1){ if(tid<o) red[tid]+=red[tid+o]; __syncthreads(); }
    float mu = red[0]*(1.0f/DMODEL); __syncthreads();
    float d0=v0-mu, d1=v1-mu, d2=v2-mu;
    red[tid] = d0*d0+d1*d1+d2*d2; __syncthreads();
    for(int o=128;o>0;o>>=1){ if(tid<o) red[tid]+=red[tid+o]; __syncthreads(); }
    float rstd = rsqrtf(red[0]*(1.0f/DMODEL) + 1e-5f);
    float* orow = out + (size_t)row*DMODEL;
    orow[tid]     = d0*rstd*gam[tid]     + bet[tid];
    orow[tid+256] = d1*rstd*gam[tid+256] + bet[tid+256];
    orow[tid+512] = d2*rstd*gam[tid+512] + bet[tid+512];
}

// ---------------- GEMM: C = A[MxK] @ B[KxN] + bias (+gelu) (+res) ----------------
// mode bit0: exact GELU, bit1: add residual res[MxN]
__global__ void __launch_bounds__(256) gemm_kernel(const float* __restrict__ A,
                                                   const float* __restrict__ Bm,
                                                   const float* __restrict__ bias,
                                                   const float* __restrict__ res,
                                                   float* __restrict__ C,
                                                   int K, int Nc, int mode){
    __shared__ float As[64*20];   // [row][k] row stride 20 (16B-aligned)
    __shared__ float Bs[16*64];   // [k][col]
    int tid = threadIdx.x;
    int tx = tid & 15, ty = tid >> 4;
    int brow = blockIdx.y*64, bcol = blockIdx.x*64;
    float acc[4][4] = {};
    int arow = tid >> 2, akq = tid & 3;      // A: 64 rows x 4 quads of k
    int bkr  = tid >> 4, bcq = tid & 15;     // B: 16 k-rows x 16 quads of col
    const float* Aptr = A + (size_t)(brow+arow)*K + akq*4;
    const float* Bptr = Bm + (size_t)bkr*Nc + bcol + bcq*4;
    for(int kt=0; kt<K; kt+=16){
        float4 va = *(const float4*)(Aptr + kt);
        float4 vb = *(const float4*)(Bptr + (size_t)kt*Nc);
        *(float4*)&As[arow*20 + akq*4] = va;
        *(float4*)&Bs[bkr*64 + bcq*4]  = vb;
        __syncthreads();
        #pragma unroll
        for(int k=0;k<16;k++){
            float a0 = As[(ty*4+0)*20+k];
            float a1 = As[(ty*4+1)*20+k];
            float a2 = As[(ty*4+2)*20+k];
            float a3 = As[(ty*4+3)*20+k];
            float4 b4 = *(const float4*)&Bs[k*64 + tx*4];
            acc[0][0]+=a0*b4.x; acc[0][1]+=a0*b4.y; acc[0][2]+=a0*b4.z; acc[0][3]+=a0*b4.w;
            acc[1][0]+=a1*b4.x; acc[1][1]+=a1*b4.y; acc[1][2]+=a1*b4.z; acc[1][3]+=a1*b4.w;
            acc[2][0]+=a2*b4.x; acc[2][1]+=a2*b4.y; acc[2][2]+=a2*b4.z; acc[2][3]+=a2*b4.w;
            acc[3][0]+=a3*b4.x; acc[3][1]+=a3*b4.y; acc[3][2]+=a3*b4.z; acc[3][3]+=a3*b4.w;
        }
        __syncthreads();
    }
    #pragma unroll
    for(int i=0;i<4;i++){
        int row = brow + ty*4 + i;
        #pragma unroll
        for(int j=0;j<4;j++){
            int col = bcol + tx*4 + j;
            float val = acc[i][j] + bias[col];
            if(mode & 1) val = 0.5f*val*(1.0f + erff(val*0.70710678118654752f));
            if(mode & 2) val += res[(size_t)row*Nc + col];
            C[(size_t)row*Nc + col] = val;
        }
    }
}

// ---------------- feature-map kernel ----------------
// grid (NCH, NH, NB). Computes dd = (data*dn) @ proj^T for a 64-row chunk of one head.
// ISQ: per-row max, write qp (incl. padding zeros). !ISQ: block atomicMax of raw dd,
// write dd - diag into g_kp (finalized by kfinal_kernel).
template<bool ISQ>
__global__ void __launch_bounds__(256) feat_kernel(const float* __restrict__ proj){
    extern __shared__ float sm[];
    float* proj_s = sm;                 // 272*65 (rows >=266 zero)
    float* qs     = proj_s + 272*65;    // 64*65
    float* pm     = qs + 64*65;         // 1024
    float* diag   = pm + 1024;          // 64
    float* mx     = diag + 64;          // 64
    int c = blockIdx.x, h = blockIdx.y, b = blockIdx.z;
    int tid = threadIdx.x;
    const float* data = ISQ ? g_q : g_k;
    float* out = ISQ ? g_qp : g_kp;

    for(int idx=tid; idx<272*64; idx+=256){
        int m = idx>>6, d = idx&63;
        proj_s[m*65+d] = (m < MF) ? proj[m*64+d] : 0.0f;
    }
    for(int idx=tid; idx<64*64; idx+=256){
        int i = idx>>6, d = idx&63;
        qs[i*65+d] = data[((size_t)(b*NSEQ + c*64 + i))*DMODEL + h*DHEAD + d];
    }
    __syncthreads();
    if(tid < 64){
        float s = 0.f;
        for(int d=0; d<64; d++){ float v = qs[tid*65+d]; s += v*v; }
        diag[tid] = 0.0625f * s;   // 0.5*dn^2 = 0.0625
    }
    __syncthreads();

    int tx = tid & 15, ty = tid >> 4;   // i = ty*4+a, m = tx + 16*mm
    float acc0[17], acc1[17], acc2[17], acc3[17];
    #pragma unroll
    for(int mm=0;mm<17;mm++){ acc0[mm]=0;acc1[mm]=0;acc2[mm]=0;acc3[mm]=0; }
    for(int d=0; d<64; d++){
        float q0 = qs[(ty*4+0)*65+d]*DN_SCALE;
        float q1 = qs[(ty*4+1)*65+d]*DN_SCALE;
        float q2 = qs[(ty*4+2)*65+d]*DN_SCALE;
        float q3 = qs[(ty*4+3)*65+d]*DN_SCALE;
        #pragma unroll
        for(int mm=0;mm<17;mm++){
            float pv = proj_s[(tx+(mm<<4))*65+d];
            acc0[mm]+=q0*pv; acc1[mm]+=q1*pv; acc2[mm]+=q2*pv; acc3[mm]+=q3*pv;
        }
    }
    size_t obase = ((size_t)(b*NH+h)*NSEQ + c*64)*MP;

    if(ISQ){
        #pragma unroll
        for(int a=0;a<4;a++){
            const float* accp = (a==0)?acc0:(a==1)?acc1:(a==2)?acc2:acc3;
            float p = -3.4e38f;
            #pragma unroll
            for(int mm=0;mm<17;mm++){ int m=tx+(mm<<4); if(m<MF) p=fmaxf(p,accp[mm]); }
            pm[(ty*4+a)*16 + tx] = p;
        }
        __syncthreads();
        if(tid < 64){
            float mv = -3.4e38f;
            for(int t=0;t<16;t++) mv = fmaxf(mv, pm[tid*16+t]);
            mx[tid] = mv;
        }
        __syncthreads();
        #pragma unroll
        for(int a=0;a<4;a++){
            const float* accp = (a==0)?acc0:(a==1)?acc1:(a==2)?acc2:acc3;
            int i = ty*4+a;
            float sub = diag[i] + mx[i];
            #pragma unroll
            for(int mm=0;mm<17;mm++){
                int m = tx+(mm<<4);
                if(m<MF) out[obase + (size_t)i*MP + m] = RATIO*(expf(accp[mm]-sub) + EPS_KER);
            }
        }
        if(tid < 128){ int i = tid>>1, m = MF + (tid&1); out[obase + (size_t)i*MP + m] = 0.0f; }
    } else {
        float bmax = -3.4e38f;
        #pragma unroll
        for(int a=0;a<4;a++){
            const float* accp = (a==0)?acc0:(a==1)?acc1:(a==2)?acc2:acc3;
            #pragma unroll
            for(int mm=0;mm<17;mm++){ int m=tx+(mm<<4); if(m<MF) bmax=fmaxf(bmax,accp[mm]); }
        }
        pm[tid] = bmax; __syncthreads();
        for(int o=128;o>0;o>>=1){ if(tid<o) pm[tid]=fmaxf(pm[tid],pm[tid+o]); __syncthreads(); }
        if(tid==0) atomicMax(&g_gmax, ford(pm[0]));
        #pragma unroll
        for(int a=0;a<4;a++){
            const float* accp = (a==0)?acc0:(a==1)?acc1:(a==2)?acc2:acc3;
            int i = ty*4+a;
            float dg = diag[i];
            #pragma unroll
            for(int mm=0;mm<17;mm++){
                int m = tx+(mm<<4);
                if(m<MF) out[obase + (size_t)i*MP + m] = accp[mm]-dg;
            }
        }
    }
}

// finalize keys: kp = ratio*(exp(stored - gmax) + eps), padding -> 0
__global__ void kfinal_kernel(){
    size_t idx = (size_t)blockIdx.x*256 + threadIdx.x;
    const size_t total = (size_t)NB*NH*NSEQ*MP;
    if(idx >= total) return;
    int m = (int)(idx % MP);
    float gm = forddec(g_gmax);
    float v = g_kp[idx];
    g_kp[idx] = (m < MF) ? RATIO*(expf(v - gm) + EPS_KER) : 0.0f;
}

// ---------------- attention phase A: per-chunk K^T V sums + k sums ----------------
__global__ void __launch_bounds__(256) phaseA_kernel(){
    extern __shared__ float sm[];
    float* kps = sm;            // 64*268
    float* vs  = kps + 64*MP;   // 64*64
    int c = blockIdx.x, h = blockIdx.y, b = blockIdx.z;
    int tid = threadIdx.x;
    int bh = b*NH + h;
    const float* kpc = g_kp + ((size_t)bh*NSEQ + c*64)*MP;
    for(int idx=tid; idx<64*MP; idx+=256) kps[idx] = kpc[idx];
    for(int idx=tid; idx<4096; idx+=256){
        int i = idx>>6, e = idx&63;
        vs[idx] = g_v[((size_t)(b*NSEQ + c*64 + i))*DMODEL + h*DHEAD + e];
    }
    __syncthreads();
    int e = tid & 63, gq = tid >> 6;     // m = gq + 4*mm
    float acc[67];
    #pragma unroll
    for(int mm=0;mm<67;mm++) acc[mm]=0.f;
    for(int j=0;j<64;j++){
        float ve = vs[j*64+e];
        #pragma unroll
        for(int mm=0;mm<67;mm++) acc[mm] += kps[j*MP + gq + (mm<<2)] * ve;
    }
    float* Sc = g_S + ((size_t)bh*NCH + c)*MF*DHEAD;
    #pragma unroll
    for(int mm=0;mm<67;mm++){
        int m = gq + (mm<<2);
        if(m < MF) Sc[(size_t)m*DHEAD + e] = acc[mm];
    }
    for(int m=tid; m<MF; m+=256){
        float s = 0.f;
        for(int j=0;j<64;j++) s += kps[j*MP + m];
        g_z[((size_t)bh*NCH + c)*MF + m] = s;
    }
}

// ---------------- phase B: in-place exclusive scan over chunks ----------------
__global__ void __launch_bounds__(256) phaseB_kernel(){
    int bh = blockIdx.x, tid = threadIdx.x;
    const int EM = MF*DHEAD;
    for(int idx=tid; idx<EM; idx+=256){
        float a = 0.f;
        for(int c=0;c<NCH;c++){
            float* p = &g_S[((size_t)bh*NCH + c)*EM + idx];
            float t = *p; *p = a; a += t;
        }
    }
    for(int idx=tid; idx<MF; idx+=256){
        float a = 0.f;
        for(int c=0;c<NCH;c++){
            float* p = &g_z[((size_t)bh*NCH + c)*MF + idx];
            float t = *p; *p = a; a += t;
        }
    }
}

// ---------------- phase C: per-chunk output ----------------
__global__ void __launch_bounds__(256) phaseC_kernel(){
    extern __shared__ float sm[];
    float* qps = sm;              // 64*268
    float* kT  = qps + 64*MP;     // 268*66 (kp transposed; later reused for S0 266*64)
    float* vs  = kT + MP*66;      // 64*64
    float* As  = vs + 4096;       // 64*65
    float* z0s = As + 64*65;      // 268
    float* den = z0s + MP;        // 64
    int c = blockIdx.x, h = blockIdx.y, b = blockIdx.z;
    int tid = threadIdx.x;
    int bh = b*NH + h;

    const float* qpc = g_qp + ((size_t)bh*NSEQ + c*64)*MP;
    const float* kpc = g_kp + ((size_t)bh*NSEQ + c*64)*MP;
    for(int idx=tid; idx<64*MP; idx+=256) qps[idx] = qpc[idx];
    for(int idx=tid; idx<64*MP; idx+=256){
        int j = idx/MP, m = idx%MP;
        kT[m*66 + j] = kpc[idx];
    }
    for(int idx=tid; idx<4096; idx+=256){
        int i = idx>>6, e = idx&63;
        vs[idx] = g_v[((size_t)(b*NSEQ + c*64 + i))*DMODEL + h*DHEAD + e];
    }
    for(int m=tid; m<MF; m+=256) z0s[m] = g_z[((size_t)bh*NCH + c)*MF + m] + EPS_DEN;
    if(tid < 2) z0s[MF+tid] = 0.0f;
    __syncthreads();

    // A[i][j] = qp[i] . kp[j]
    int j = tid & 63, ib = tid >> 6;     // i = ib + 4*k
    float accA[16];
    #pragma unroll
    for(int k=0;k<16;k++) accA[k]=0.f;
    for(int m=0;m<MF;m++){
        float kv = kT[m*66 + j];
        #pragma unroll
        for(int k=0;k<16;k++) accA[k] += qps[(ib+(k<<2))*MP + m] * kv;
    }
    #pragma unroll
    for(int k=0;k<16;k++) As[(ib+(k<<2))*65 + j] = accA[k];
    __syncthreads();

    // den (threads < 64) while everyone loads S0 into kT
    if(tid < 64){
        int i = tid;
        float s = 0.f;
        for(int m=0;m<MF;m++) s += qps[i*MP+m]*z0s[m];
        for(int jj=0;jj<=i;jj++) s += As[i*65+jj];
        den[i] = s;
    }
    const float* Sc = g_S + ((size_t)bh*NCH + c)*MF*DHEAD;
    for(int idx=tid; idx<MF*DHEAD; idx+=256) kT[idx] = Sc[idx];
    __syncthreads();

    // out[i][e] = qp[i] . S0[:,e] + sum_{j<=i} A[i][j] v[j][e], / den[i]
    int e = tid & 63;
    float acco[16];
    #pragma unroll
    for(int k=0;k<16;k++) acco[k]=0.f;
    for(int m=0;m<MF;m++){
        float sv = kT[m*DHEAD + e];
        #pragma unroll
        for(int k=0;k<16;k++) acco[k] += qps[(ib+(k<<2))*MP + m] * sv;
    }
    for(int jj=0;jj<64;jj++){
        float vv = vs[jj*64 + e];
        #pragma unroll
        for(int k=0;k<16;k++){
            int i = ib + (k<<2);
            if(jj <= i) acco[k] += As[i*65 + jj] * vv;
        }
    }
    #pragma unroll
    for(int k=0;k<16;k++){
        int i = ib + (k<<2);
        g_o[((size_t)(b*NSEQ + c*64 + i))*DMODEL + h*DHEAD + e] = acco[k] / den[i];
    }
}

// ---------------- host ----------------
#define SMEM_FEAT ((272*65 + 64*65 + 1024 + 64 + 64)*4)
#define SMEM_A    ((64*MP + 64*64)*4)
#define SMEM_C    ((64*MP + MP*66 + 4096 + 64*65 + MP + 64)*4)

extern "C" void kernel_launch(void* const* d_in, const int* in_sizes, int n_in,
                              void* d_out, int out_size){
    const float* x     = (const float*)d_in[0];
    const float* ln1_g = (const float*)d_in[1];
    const float* ln1_b = (const float*)d_in[2];
    const float* Wq    = (const float*)d_in[3];
    const float* bq    = (const float*)d_in[4];
    const float* Wk    = (const float*)d_in[5];
    const float* bk    = (const float*)d_in[6];
    const float* Wv    = (const float*)d_in[7];
    const float* bv    = (const float*)d_in[8];
    const float* Wo    = (const float*)d_in[9];
    const float* bo    = (const float*)d_in[10];
    const float* proj  = (const float*)d_in[11];
    const float* ln2_g = (const float*)d_in[12];
    const float* ln2_b = (const float*)d_in[13];
    const float* W1    = (const float*)d_in[14];
    const float* b1    = (const float*)d_in[15];
    const float* W2    = (const float*)d_in[16];
    const float* b2    = (const float*)d_in[17];
    float* out = (float*)d_out;

    void *ph, *pq, *pk, *pv, *po, *px2, *ph2, *pff;
    cudaGetSymbolAddress(&ph,  g_h);
    cudaGetSymbolAddress(&pq,  g_q);
    cudaGetSymbolAddress(&pk,  g_k);
    cudaGetSymbolAddress(&pv,  g_v);
    cudaGetSymbolAddress(&po,  g_o);
    cudaGetSymbolAddress(&px2, g_x2);
    cudaGetSymbolAddress(&ph2, g_h2);
    cudaGetSymbolAddress(&pff, g_ff);

    cudaFuncSetAttribute(feat_kernel<true>,  cudaFuncAttributeMaxDynamicSharedMemorySize, SMEM_FEAT);
    cudaFuncSetAttribute(feat_kernel<false>, cudaFuncAttributeMaxDynamicSharedMemorySize, SMEM_FEAT);
    cudaFuncSetAttribute(phaseA_kernel, cudaFuncAttributeMaxDynamicSharedMemorySize, SMEM_A);
    cudaFuncSetAttribute(phaseC_kernel, cudaFuncAttributeMaxDynamicSharedMemorySize, SMEM_C);

    dim3 gAttn(NCH, NH, NB);

    init_kernel<<<1,1>>>();
    ln_kernel<<<ROWS,256>>>(x, ln1_g, ln1_b, (float*)ph);

    gemm_kernel<<<dim3(DMODEL/64, ROWS/64), 256>>>((const float*)ph, Wq, bq, nullptr, (float*)pq, DMODEL, DMODEL, 0);
    gemm_kernel<<<dim3(DMODEL/64, ROWS/64), 256>>>((const float*)ph, Wk, bk, nullptr, (float*)pk, DMODEL, DMODEL, 0);
    gemm_kernel<<<dim3(DMODEL/64, ROWS/64), 256>>>((const float*)ph, Wv, bv, nullptr, (float*)pv, DMODEL, DMODEL, 0);

    feat_kernel<true ><<<gAttn, 256, SMEM_FEAT>>>(proj);
    feat_kernel<false><<<gAttn, 256, SMEM_FEAT>>>(proj);
    {
        size_t total = (size_t)NB*NH*NSEQ*MP;
        kfinal_kernel<<<(unsigned)((total+255)/256), 256>>>();
    }

    phaseA_kernel<<<gAttn, 256, SMEM_A>>>();
    phaseB_kernel<<<NB*NH, 256>>>();
    phaseC_kernel<<<gAttn, 256, SMEM_C>>>();

    gemm_kernel<<<dim3(DMODEL/64, ROWS/64), 256>>>((const float*)po, Wo, bo, x, (float*)px2, DMODEL, DMODEL, 2);
    ln_kernel<<<ROWS,256>>>((const float*)px2, ln2_g, ln2_b, (float*)ph2);
    gemm_kernel<<<dim3(NFF/64, ROWS/64), 256>>>((const float*)ph2, W1, b1, nullptr, (float*)pff, DMODEL, NFF, 1);
    gemm_kernel<<<dim3(DMODEL/64, ROWS/64), 256>>>((const float*)pff, W2, b2, (const float*)px2, out, NFF, DMODEL, 2);
}

// round 3
// speedup vs baseline: 1.5378x; 1.5378x over previous
#include <cuda_runtime.h>
#include <math.h>

// ---------------- problem constants ----------------
#define NB     2
#define NSEQ   2048
#define DMODEL 768
#define NH     12
#define DHEAD  64
#define MF     266        // random features
#define MP     268        // padded (multiple of 4)
#define NFF    3072
#define NCH    32         // chunks
#define CHK    64         // chunk length
#define ROWS   (NB*NSEQ)  // 4096

#define DN_SCALE   0.3535533905932738f      // 64^-0.25
#define RATIO      0.06131393394849658f     // 266^-0.5
#define EPS_KER    1e-4f
#define EPS_DEN    1e-6f

// ---------------- scratch (device globals; allocation-free) ----------------
__device__ float g_h [ROWS*DMODEL];
__device__ float g_q [ROWS*DMODEL];
__device__ float g_k [ROWS*DMODEL];
__device__ float g_v [ROWS*DMODEL];
__device__ float g_qp[NB*NH*NSEQ*MP];
__device__ float g_kp[NB*NH*NSEQ*MP];
__device__ float g_S [NB*NH*NCH*MF*DHEAD];
__device__ float g_z [NB*NH*NCH*MF];
__device__ float g_o [ROWS*DMODEL];
__device__ float g_x2[ROWS*DMODEL];
__device__ float g_h2[ROWS*DMODEL];
__device__ float g_ff[ROWS*NFF];
__device__ unsigned g_gmax;

// ---------------- helpers ----------------
__device__ __forceinline__ unsigned ford(float f){
    unsigned u = __float_as_uint(f);
    return (u & 0x80000000u) ? ~u : (u | 0x80000000u);
}
__device__ __forceinline__ float forddec(unsigned u){
    return (u & 0x80000000u) ? __uint_as_float(u & 0x7fffffffu) : __uint_as_float(~u);
}
__device__ __forceinline__ float f2tf(float f){
    unsigned r;
    asm("cvt.rna.tf32.f32 %0, %1;" : "=r"(r) : "f"(f));
    return __uint_as_float(r);
}
__device__ __forceinline__ void mma_tf32(float* c, const unsigned* a, const unsigned* b){
    asm volatile("mma.sync.aligned.m16n8k8.row.col.f32.tf32.tf32.f32 "
        "{%0,%1,%2,%3}, {%4,%5,%6,%7}, {%8,%9}, {%0,%1,%2,%3};"
        : "+f"(c[0]), "+f"(c[1]), "+f"(c[2]), "+f"(c[3])
        : "r"(a[0]), "r"(a[1]), "r"(a[2]), "r"(a[3]), "r"(b[0]), "r"(b[1]));
}

__global__ void init_kernel(){ g_gmax = 0u; }

// ---------------- LayerNorm: one block per row (768 = 3*256) ----------------
__global__ void __launch_bounds__(256) ln_kernel(const float* __restrict__ x,
                                                 const float* __restrict__ gam,
                                                 const float* __restrict__ bet,
                                                 float* __restrict__ out){
    int row = blockIdx.x, tid = threadIdx.x;
    const float* xr = x + (size_t)row*DMODEL;
    float v0 = xr[tid], v1 = xr[tid+256], v2 = xr[tid+512];
    __shared__ float red[256];
    red[tid] = v0+v1+v2; __syncthreads();
    for(int o=128;o>0;o>>=1){ if(tid<o) red[tid]+=red[tid+o]; __syncthreads(); }
    float mu = red[0]*(1.0f/DMODEL); __syncthreads();
    float d0=v0-mu, d1=v1-mu, d2=v2-mu;
    red[tid] = d0*d0+d1*d1+d2*d2; __syncthreads();
    for(int o=128;o>0;o>>=1){ if(tid<o) red[tid]+=red[tid+o]; __syncthreads(); }
    float rstd = rsqrtf(red[0]*(1.0f/DMODEL) + 1e-5f);
    float* orow = out + (size_t)row*DMODEL;
    orow[tid]     = d0*rstd*gam[tid]     + bet[tid];
    orow[tid+256] = d1*rstd*gam[tid+256] + bet[tid+256];
    orow[tid+512] = d2*rstd*gam[tid+512] + bet[tid+512];
}

// ---------------- TF32 tensor-core GEMM ----------------
// C[MxN] = A[MxK] @ B[KxN] + bias (+gelu) (+res). Tile 128x64x16, 8 warps.
// Warp grid 4(M) x 2(N); each warp 32x32 via 2x4 m16n8k8 fragments.
// mode bit0: exact GELU, bit1: add residual res[MxN]
__global__ void __launch_bounds__(256) gemm_kernel(const float* __restrict__ A,
                                                   const float* __restrict__ Bm,
                                                   const float* __restrict__ bias,
                                                   const float* __restrict__ res,
                                                   float* __restrict__ C,
                                                   int K, int Nc, int mode){
    __shared__ float As[128*20];   // [m][k], row stride 20 (16B aligned, conflict-free frags)
    __shared__ float Bs[16*72];    // [k][n], row stride 72
    int tid = threadIdx.x, lane = tid & 31, warp = tid >> 5;
    int wm = warp >> 1, wn = warp & 1;
    int brow = blockIdx.y*128, bcol = blockIdx.x*64;

    // global load mapping
    int arow = tid >> 1, acol = (tid & 1)*8;     // 128 rows x 16 k: 8 floats/thread
    int bkr  = tid >> 4, bcq  = tid & 15;        // 16 k-rows x 64 n: 4 floats/thread
    const float* Ap = A  + (size_t)(brow+arow)*K + acol;
    const float* Bp = Bm + (size_t)bkr*Nc + bcol + bcq*4;

    float acc[2][4][4];
    #pragma unroll
    for(int i=0;i<2;i++) for(int j=0;j<4;j++) for(int r=0;r<4;r++) acc[i][j][r]=0.f;

    int lg = lane >> 2, lq = lane & 3;
    for(int kt=0; kt<K; kt+=16){
        float4 va0 = *(const float4*)(Ap + kt);
        float4 va1 = *(const float4*)(Ap + kt + 4);
        float4 vb  = *(const float4*)(Bp + (size_t)kt*Nc);
        float* asd = &As[arow*20 + acol];
        asd[0]=f2tf(va0.x); asd[1]=f2tf(va0.y); asd[2]=f2tf(va0.z); asd[3]=f2tf(va0.w);
        asd[4]=f2tf(va1.x); asd[5]=f2tf(va1.y); asd[6]=f2tf(va1.z); asd[7]=f2tf(va1.w);
        float* bsd = &Bs[bkr*72 + bcq*4];
        bsd[0]=f2tf(vb.x); bsd[1]=f2tf(vb.y); bsd[2]=f2tf(vb.z); bsd[3]=f2tf(vb.w);
        __syncthreads();

        #pragma unroll
        for(int kk=0; kk<16; kk+=8){
            unsigned af[2][4];
            #pragma unroll
            for(int mf=0; mf<2; mf++){
                int m0 = wm*32 + mf*16 + lg;
                af[mf][0] = __float_as_uint(As[(m0  )*20 + kk + lq    ]);
                af[mf][1] = __float_as_uint(As[(m0+8)*20 + kk + lq    ]);
                af[mf][2] = __float_as_uint(As[(m0  )*20 + kk + lq + 4]);
                af[mf][3] = __float_as_uint(As[(m0+8)*20 + kk + lq + 4]);
            }
            unsigned bf[4][2];
            #pragma unroll
            for(int nf=0; nf<4; nf++){
                int n0 = wn*32 + nf*8 + lg;
                bf[nf][0] = __float_as_uint(Bs[(kk + lq    )*72 + n0]);
                bf[nf][1] = __float_as_uint(Bs[(kk + lq + 4)*72 + n0]);
            }
            #pragma unroll
            for(int mf=0; mf<2; mf++)
                #pragma unroll
                for(int nf=0; nf<4; nf++)
                    mma_tf32(acc[mf][nf], af[mf], bf[nf]);
        }
        __syncthreads();
    }

    // epilogue
    #pragma unroll
    for(int mf=0; mf<2; mf++){
        #pragma unroll
        for(int nf=0; nf<4; nf++){
            int row0 = brow + wm*32 + mf*16 + lg;
            int col0 = bcol + wn*32 + nf*8 + lq*2;
            #pragma unroll
            for(int r=0; r<4; r++){
                int row = row0 + (r>>1)*8;
                int col = col0 + (r&1);
                float val = acc[mf][nf][r] + bias[col];
                if(mode & 1) val = 0.5f*val*(1.0f + erff(val*0.70710678118654752f));
                if(mode & 2) val += res[(size_t)row*Nc + col];
                C[(size_t)row*Nc + col] = val;
            }
        }
    }
}

// ---------------- feature-map kernel ----------------
template<bool ISQ>
__global__ void __launch_bounds__(256) feat_kernel(const float* __restrict__ proj){
    extern __shared__ float sm[];
    float* proj_s = sm;                 // 272*65 (rows >=266 zero)
    float* qs     = proj_s + 272*65;    // 64*65
    float* pm     = qs + 64*65;         // 1024
    float* diag   = pm + 1024;          // 64
    float* mx     = diag + 64;          // 64
    int c = blockIdx.x, h = blockIdx.y, b = blockIdx.z;
    int tid = threadIdx.x;
    const float* data = ISQ ? g_q : g_k;
    float* out = ISQ ? g_qp : g_kp;

    for(int idx=tid; idx<272*64; idx+=256){
        int m = idx>>6, d = idx&63;
        proj_s[m*65+d] = (m < MF) ? proj[m*64+d] : 0.0f;
    }
    for(int idx=tid; idx<64*64; idx+=256){
        int i = idx>>6, d = idx&63;
        qs[i*65+d] = data[((size_t)(b*NSEQ + c*64 + i))*DMODEL + h*DHEAD + d];
    }
    __syncthreads();
    if(tid < 64){
        float s = 0.f;
        for(int d=0; d<64; d++){ float v = qs[tid*65+d]; s += v*v; }
        diag[tid] = 0.0625f * s;
    }
    __syncthreads();

    int tx = tid & 15, ty = tid >> 4;
    float acc0[17], acc1[17], acc2[17], acc3[17];
    #pragma unroll
    for(int mm=0;mm<17;mm++){ acc0[mm]=0;acc1[mm]=0;acc2[mm]=0;acc3[mm]=0; }
    for(int d=0; d<64; d++){
        float q0 = qs[(ty*4+0)*65+d]*DN_SCALE;
        float q1 = qs[(ty*4+1)*65+d]*DN_SCALE;
        float q2 = qs[(ty*4+2)*65+d]*DN_SCALE;
        float q3 = qs[(ty*4+3)*65+d]*DN_SCALE;
        #pragma unroll
        for(int mm=0;mm<17;mm++){
            float pv = proj_s[(tx+(mm<<4))*65+d];
            acc0[mm]+=q0*pv; acc1[mm]+=q1*pv; acc2[mm]+=q2*pv; acc3[mm]+=q3*pv;
        }
    }
    size_t obase = ((size_t)(b*NH+h)*NSEQ + c*64)*MP;

    if(ISQ){
        #pragma unroll
        for(int a=0;a<4;a++){
            const float* accp = (a==0)?acc0:(a==1)?acc1:(a==2)?acc2:acc3;
            float p = -3.4e38f;
            #pragma unroll
            for(int mm=0;mm<17;mm++){ int m=tx+(mm<<4); if(m<MF) p=fmaxf(p,accp[mm]); }
            pm[(ty*4+a)*16 + tx] = p;
        }
        __syncthreads();
        if(tid < 64){
            float mv = -3.4e38f;
            for(int t=0;t<16;t++) mv = fmaxf(mv, pm[tid*16+t]);
            mx[tid] = mv;
        }
        __syncthreads();
        #pragma unroll
        for(int a=0;a<4;a++){
            const float* accp = (a==0)?acc0:(a==1)?acc1:(a==2)?acc2:acc3;
            int i = ty*4+a;
            float sub = diag[i] + mx[i];
            #pragma unroll
            for(int mm=0;mm<17;mm++){
                int m = tx+(mm<<4);
                if(m<MF) out[obase + (size_t)i*MP + m] = RATIO*(expf(accp[mm]-sub) + EPS_KER);
            }
        }
        if(tid < 128){ int i = tid>>1, m = MF + (tid&1); out[obase + (size_t)i*MP + m] = 0.0f; }
    } else {
        float bmax = -3.4e38f;
        #pragma unroll
        for(int a=0;a<4;a++){
            const float* accp = (a==0)?acc0:(a==1)?acc1:(a==2)?acc2:acc3;
            #pragma unroll
            for(int mm=0;mm<17;mm++){ int m=tx+(mm<<4); if(m<MF) bmax=fmaxf(bmax,accp[mm]); }
        }
        pm[tid] = bmax; __syncthreads();
        for(int o=128;o>0;o>>=1){ if(tid<o) pm[tid]=fmaxf(pm[tid],pm[tid+o]); __syncthreads(); }
        if(tid==0) atomicMax(&g_gmax, ford(pm[0]));
        #pragma unroll
        for(int a=0;a<4;a++){
            const float* accp = (a==0)?acc0:(a==1)?acc1:(a==2)?acc2:acc3;
            int i = ty*4+a;
            float dg = diag[i];
            #pragma unroll
            for(int mm=0;mm<17;mm++){
                int m = tx+(mm<<4);
                if(m<MF) out[obase + (size_t)i*MP + m] = accp[mm]-dg;
            }
        }
    }
}

// finalize keys: kp = ratio*(exp(stored - gmax) + eps), padding -> 0
__global__ void kfinal_kernel(){
    size_t idx = (size_t)blockIdx.x*256 + threadIdx.x;
    const size_t total = (size_t)NB*NH*NSEQ*MP;
    if(idx >= total) return;
    int m = (int)(idx % MP);
    float gm = forddec(g_gmax);
    float v = g_kp[idx];
    g_kp[idx] = (m < MF) ? RATIO*(expf(v - gm) + EPS_KER) : 0.0f;
}

// ---------------- attention phase A: per-chunk K^T V sums + k sums ----------------
__global__ void __launch_bounds__(256) phaseA_kernel(){
    extern __shared__ float sm[];
    float* kps = sm;            // 64*268
    float* vs  = kps + 64*MP;   // 64*64
    int c = blockIdx.x, h = blockIdx.y, b = blockIdx.z;
    int tid = threadIdx.x;
    int bh = b*NH + h;
    const float* kpc = g_kp + ((size_t)bh*NSEQ + c*64)*MP;
    for(int idx=tid; idx<64*MP; idx+=256) kps[idx] = kpc[idx];
    for(int idx=tid; idx<4096; idx+=256){
        int i = idx>>6, e = idx&63;
        vs[idx] = g_v[((size_t)(b*NSEQ + c*64 + i))*DMODEL + h*DHEAD + e];
    }
    __syncthreads();
    int e = tid & 63, gq = tid >> 6;
    float acc[67];
    #pragma unroll
    for(int mm=0;mm<67;mm++) acc[mm]=0.f;
    for(int j=0;j<64;j++){
        float ve = vs[j*64+e];
        #pragma unroll
        for(int mm=0;mm<67;mm++) acc[mm] += kps[j*MP + gq + (mm<<2)] * ve;
    }
    float* Sc = g_S + ((size_t)bh*NCH + c)*MF*DHEAD;
    #pragma unroll
    for(int mm=0;mm<67;mm++){
        int m = gq + (mm<<2);
        if(m < MF) Sc[(size_t)m*DHEAD + e] = acc[mm];
    }
    for(int m=tid; m<MF; m+=256){
        float s = 0.f;
        for(int j=0;j<64;j++) s += kps[j*MP + m];
        g_z[((size_t)bh*NCH + c)*MF + m] = s;
    }
}

// ---------------- phase B: in-place exclusive scan over chunks ----------------
__global__ void __launch_bounds__(256) phaseB_kernel(){
    int bh = blockIdx.x, tid = threadIdx.x;
    const int EM = MF*DHEAD;
    for(int idx=tid; idx<EM; idx+=256){
        float a = 0.f;
        for(int c=0;c<NCH;c++){
            float* p = &g_S[((size_t)bh*NCH + c)*EM + idx];
            float t = *p; *p = a; a += t;
        }
    }
    for(int idx=tid; idx<MF; idx+=256){
        float a = 0.f;
        for(int c=0;c<NCH;c++){
            float* p = &g_z[((size_t)bh*NCH + c)*MF + idx];
            float t = *p; *p = a; a += t;
        }
    }
}

// ---------------- phase C: per-chunk output ----------------
__global__ void __launch_bounds__(256) phaseC_kernel(){
    extern __shared__ float sm[];
    float* qps = sm;              // 64*268
    float* kT  = qps + 64*MP;     // 268*66 (kp transposed; later reused for S0)
    float* vs  = kT + MP*66;      // 64*64
    float* As  = vs + 4096;       // 64*65
    float* z0s = As + 64*65;      // 268
    float* den = z0s + MP;        // 64
    int c = blockIdx.x, h = blockIdx.y, b = blockIdx.z;
    int tid = threadIdx.x;
    int bh = b*NH + h;

    const float* qpc = g_qp + ((size_t)bh*NSEQ + c*64)*MP;
    const float* kpc = g_kp + ((size_t)bh*NSEQ + c*64)*MP;
    for(int idx=tid; idx<64*MP; idx+=256) qps[idx] = qpc[idx];
    for(int idx=tid; idx<64*MP; idx+=256){
        int j = idx/MP, m = idx%MP;
        kT[m*66 + j] = kpc[idx];
    }
    for(int idx=tid; idx<4096; idx+=256){
        int i = idx>>6, e = idx&63;
        vs[idx] = g_v[((size_t)(b*NSEQ + c*64 + i))*DMODEL + h*DHEAD + e];
    }
    for(int m=tid; m<MF; m+=256) z0s[m] = g_z[((size_t)bh*NCH + c)*MF + m] + EPS_DEN;
    if(tid < 2) z0s[MF+tid] = 0.0f;
    __syncthreads();

    int j = tid & 63, ib = tid >> 6;
    float accA[16];
    #pragma unroll
    for(int k=0;k<16;k++) accA[k]=0.f;
    for(int m=0;m<MF;m++){
        float kv = kT[m*66 + j];
        #pragma unroll
        for(int k=0;k<16;k++) accA[k] += qps[(ib+(k<<2))*MP + m] * kv;
    }
    #pragma unroll
    for(int k=0;k<16;k++) As[(ib+(k<<2))*65 + j] = accA[k];
    __syncthreads();

    if(tid < 64){
        int i = tid;
        float s = 0.f;
        for(int m=0;m<MF;m++) s += qps[i*MP+m]*z0s[m];
        for(int jj=0;jj<=i;jj++) s += As[i*65+jj];
        den[i] = s;
    }
    const float* Sc = g_S + ((size_t)bh*NCH + c)*MF*DHEAD;
    for(int idx=tid; idx<MF*DHEAD; idx+=256) kT[idx] = Sc[idx];
    __syncthreads();

    int e = tid & 63;
    float acco[16];
    #pragma unroll
    for(int k=0;k<16;k++) acco[k]=0.f;
    for(int m=0;m<MF;m++){
        float sv = kT[m*DHEAD + e];
        #pragma unroll
        for(int k=0;k<16;k++) acco[k] += qps[(ib+(k<<2))*MP + m] * sv;
    }
    for(int jj=0;jj<64;jj++){
        float vv = vs[jj*64 + e];
        #pragma unroll
        for(int k=0;k<16;k++){
            int i = ib + (k<<2);
            if(jj <= i) acco[k] += As[i*65 + jj] * vv;
        }
    }
    #pragma unroll
    for(int k=0;k<16;k++){
        int i = ib + (k<<2);
        g_o[((size_t)(b*NSEQ + c*64 + i))*DMODEL + h*DHEAD + e] = acco[k] / den[i];
    }
}

// ---------------- host ----------------
#define SMEM_FEAT ((272*65 + 64*65 + 1024 + 64 + 64)*4)
#define SMEM_A    ((64*MP + 64*64)*4)
#define SMEM_C    ((64*MP + MP*66 + 4096 + 64*65 + MP + 64)*4)

extern "C" void kernel_launch(void* const* d_in, const int* in_sizes, int n_in,
                              void* d_out, int out_size){
    const float* x     = (const float*)d_in[0];
    const float* ln1_g = (const float*)d_in[1];
    const float* ln1_b = (const float*)d_in[2];
    const float* Wq    = (const float*)d_in[3];
    const float* bq    = (const float*)d_in[4];
    const float* Wk    = (const float*)d_in[5];
    const float* bk    = (const float*)d_in[6];
    const float* Wv    = (const float*)d_in[7];
    const float* bv    = (const float*)d_in[8];
    const float* Wo    = (const float*)d_in[9];
    const float* bo    = (const float*)d_in[10];
    const float* proj  = (const float*)d_in[11];
    const float* ln2_g = (const float*)d_in[12];
    const float* ln2_b = (const float*)d_in[13];
    const float* W1    = (const float*)d_in[14];
    const float* b1    = (const float*)d_in[15];
    const float* W2    = (const float*)d_in[16];
    const float* b2    = (const float*)d_in[17];
    float* out = (float*)d_out;

    void *ph, *pq, *pk, *pv, *po, *px2, *ph2, *pff;
    cudaGetSymbolAddress(&ph,  g_h);
    cudaGetSymbolAddress(&pq,  g_q);
    cudaGetSymbolAddress(&pk,  g_k);
    cudaGetSymbolAddress(&pv,  g_v);
    cudaGetSymbolAddress(&po,  g_o);
    cudaGetSymbolAddress(&px2, g_x2);
    cudaGetSymbolAddress(&ph2, g_h2);
    cudaGetSymbolAddress(&pff, g_ff);

    cudaFuncSetAttribute(feat_kernel<true>,  cudaFuncAttributeMaxDynamicSharedMemorySize, SMEM_FEAT);
    cudaFuncSetAttribute(feat_kernel<false>, cudaFuncAttributeMaxDynamicSharedMemorySize, SMEM_FEAT);
    cudaFuncSetAttribute(phaseA_kernel, cudaFuncAttributeMaxDynamicSharedMemorySize, SMEM_A);
    cudaFuncSetAttribute(phaseC_kernel, cudaFuncAttributeMaxDynamicSharedMemorySize, SMEM_C);

    dim3 gAttn(NCH, NH, NB);

    init_kernel<<<1,1>>>();
    ln_kernel<<<ROWS,256>>>(x, ln1_g, ln1_b, (float*)ph);

    gemm_kernel<<<dim3(DMODEL/64, ROWS/128), 256>>>((const float*)ph, Wq, bq, nullptr, (float*)pq, DMODEL, DMODEL, 0);
    gemm_kernel<<<dim3(DMODEL/64, ROWS/128), 256>>>((const float*)ph, Wk, bk, nullptr, (float*)pk, DMODEL, DMODEL, 0);
    gemm_kernel<<<dim3(DMODEL/64, ROWS/128), 256>>>((const float*)ph, Wv, bv, nullptr, (float*)pv, DMODEL, DMODEL, 0);

    feat_kernel<true ><<<gAttn, 256, SMEM_FEAT>>>(proj);
    feat_kernel<false><<<gAttn, 256, SMEM_FEAT>>>(proj);
    {
        size_t total = (size_t)NB*NH*NSEQ*MP;
        kfinal_kernel<<<(unsigned)((total+255)/256), 256>>>();
    }

    phaseA_kernel<<<gAttn, 256, SMEM_A>>>();
    phaseB_kernel<<<NB*NH, 256>>>();
    phaseC_kernel<<<gAttn, 256, SMEM_C>>>();

    gemm_kernel<<<dim3(DMODEL/64, ROWS/128), 256>>>((const float*)po, Wo, bo, x, (float*)px2, DMODEL, DMODEL, 2);
    ln_kernel<<<ROWS,256>>>((const float*)px2, ln2_g, ln2_b, (float*)ph2);
    gemm_kernel<<<dim3(NFF/64, ROWS/128), 256>>>((const float*)ph2, W1, b1, nullptr, (float*)pff, DMODEL, NFF, 1);
    gemm_kernel<<<dim3(DMODEL/64, ROWS/128), 256>>>((const float*)pff, W2, b2, (const float*)px2, out, NFF, DMODEL, 2);
}